// round 14
// baseline (speedup 1.0000x reference)
#include <cuda_runtime.h>
#include <cuda_fp16.h>
#include <cstdint>

// Fused 2-layer MLP, pure fp16 mma.sync + LDSM, warp-specialized:
//   warps 0-7  (A): GEMM1; X fragments held in REGISTERS for all 16 chunks
//   warps 8-15 (B): GEMM2 accumulator
// Double-buffered hs, named barriers (R9 protocol), cp.async weights.
//   out = relu(relu(X@W0+b0)@W1+b1); rel_err ~4.2e-4 (validated R9/R11/R13).

#define K1   192
#define HID  1024
#define EMB  256
#define NCH  16

#define XS_W  100     // words/row (100%32=4 -> conflict-free LDSM phases)
#define W0S_W 100
#define HS_W  36
#define W1S_W 36

// smem byte offsets (111616 total, 1 CTA of 512 threads)
#define SM_B0S 0
#define SM_B1S 4096
#define SM_XS  5120                   // 64*400  = 25600
#define SM_W0S 30720                  // 64*400  = 25600
#define SM_HS  56320                  // 2 x 64*144*... = 2*9216 = 18432
#define SM_W1S 74752                  // 256*144 = 36864
#define SM_TOTAL 111616

#define HSB 9216      // hs buffer stride (bytes)

// named barriers
#define BFULL(p) (1 + (p))
#define BFREE(p) (3 + (p))
#define BINTA 5
#define BINTB 6

#define BAR_SYNC(id, n)   asm volatile("bar.sync %0, %1;"   :: "r"(id), "r"(n) : "memory")
#define BAR_ARRIVE(id, n) asm volatile("bar.arrive %0, %1;" :: "r"(id), "r"(n) : "memory")

__device__ __align__(16) __half g_B1[HID * K1];     // W0^T [n][k]
__device__ __align__(16) __half g_B2[EMB * HID];    // W1^T [n][k]

__device__ __forceinline__ void cpa16(uint32_t dst, const void* src) {
    asm volatile("cp.async.cg.shared.global [%0], [%1], 16;" :: "r"(dst), "l"(src) : "memory");
}
#define CP_COMMIT() asm volatile("cp.async.commit_group;" ::: "memory")
#define CP_WAIT0()  asm volatile("cp.async.wait_group 0;" ::: "memory")

__device__ __forceinline__ uint32_t smem_u32(const void* p) {
    uint32_t a;
    asm("{ .reg .u64 t; cvta.to.shared.u64 t, %1; cvt.u32.u64 %0, t; }" : "=r"(a) : "l"(p));
    return a;
}

__device__ __forceinline__ void ldsm4(uint32_t& r0, uint32_t& r1, uint32_t& r2,
                                      uint32_t& r3, uint32_t addr)
{
    asm volatile("ldmatrix.sync.aligned.m8n8.x4.shared.b16 {%0,%1,%2,%3}, [%4];"
        : "=r"(r0), "=r"(r1), "=r"(r2), "=r"(r3) : "r"(addr));
}

__device__ __forceinline__ void mma16816(float* c,
    uint32_t a0, uint32_t a1, uint32_t a2, uint32_t a3, uint32_t b0, uint32_t b1)
{
    asm volatile("mma.sync.aligned.m16n8k16.row.col.f32.f16.f16.f32 "
        "{%0,%1,%2,%3}, {%4,%5,%6,%7}, {%8,%9}, {%0,%1,%2,%3};"
        : "+f"(c[0]), "+f"(c[1]), "+f"(c[2]), "+f"(c[3])
        : "r"(a0), "r"(a1), "r"(a2), "r"(a3), "r"(b0), "r"(b1));
}

__device__ __forceinline__ uint32_t pack2(float x, float y) {
    __half2 h = __halves2half2(__float2half_rn(x), __float2half_rn(y));
    return *(uint32_t*)&h;
}

// ---------------- weight prep: fp16, transposed to [n][k] ----------------
__global__ void prep_kernel(const float* __restrict__ W0, const float* __restrict__ W1) {
    int stride = gridDim.x * blockDim.x;
    int t0 = blockIdx.x * blockDim.x + threadIdx.x;
    for (int i = t0; i < HID * K1; i += stride) {
        int n = i / K1, k = i % K1;
        g_B1[n * K1 + k] = __float2half_rn(W0[k * HID + n]);
    }
    for (int i = t0; i < EMB * HID; i += stride) {
        int n = i / HID, k = i % HID;
        g_B2[n * HID + k] = __float2half_rn(W1[k * EMB + n]);
    }
}

// ---------------- per-group chunk loaders (256 threads each) ----------------
__device__ __forceinline__ void load_w0(uint32_t sb, int c, int gtid) {
    const __half* base = g_B1 + (size_t)c * 64 * K1;
    #pragma unroll
    for (int i = gtid; i < 1536; i += 256) {          // 64 rows x 24 x 16B
        int n = i / 24, u = i % 24;
        cpa16(sb + SM_W0S + n * 400 + u * 16, base + n * K1 + u * 8);
    }
    CP_COMMIT();
}
__device__ __forceinline__ void load_w1(uint32_t sb, int c, int gtid) {
    const __half* base = g_B2 + c * 64;
    #pragma unroll
    for (int i = gtid; i < 2048; i += 256) {          // 256 rows x 8 x 16B
        int n = i / 8, u = i % 8;
        cpa16(sb + SM_W1S + n * 144 + u * 16, base + n * HID + u * 8);
    }
    CP_COMMIT();
}

// ---------------- main fused kernel ----------------
__global__ void __launch_bounds__(512, 1)
mlp_kernel(const float* __restrict__ x, const float* __restrict__ b0,
           const float* __restrict__ b1, float* __restrict__ out)
{
    extern __shared__ char smem[];
    const uint32_t sb = smem_u32(smem);
    const int tid  = threadIdx.x;
    const int lane = tid & 31;
    const int w    = tid >> 5;
    const int gtid = tid & 255;
    const int r    = lane >> 2;
    const int q    = lane & 3;
    const bool isA = (w < 8);

    const int slice   = blockIdx.x >> 1;
    const int tokbase = (blockIdx.x & 1) * 64;

    uint32_t* xsw = (uint32_t*)(smem + SM_XS);
    uint32_t* hsw = (uint32_t*)(smem + SM_HS);
    float*    b0s = (float*)(smem + SM_B0S);
    float*    b1s = (float*)(smem + SM_B1S);

    // group-owned prefetch of chunk 0 weights
    if (isA) load_w0(sb, 0, gtid);
    else     load_w1(sb, 0, gtid);

    // X slice -> Xs (fp16, 96 words per row)
    {
        const float2* x2 = (const float2*)(x + (size_t)slice * 24576);
        #pragma unroll 4
        for (int i = tid; i < 6144; i += 512) {
            int m = i / 96, u = i % 96;
            int ch = u >> 5, bp = u & 31;
            float2 v = x2[(ch * 8192 + (tokbase + m) * 64) / 2 + bp];
            xsw[m * XS_W + ch * 32 + bp] = pack2(v.x, v.y);
        }
        for (int i = tid; i < 1024; i += 512) b0s[i] = b0[i];
        for (int i = tid; i < 256;  i += 512) b1s[i] = b1[i];
    }
    __syncthreads();      // X + biases staged; groups diverge

    if (isA) {
        // ================= group A: GEMM1 producer =================
        const int m1 = (w >> 1) * 16;
        const int n1 = (w & 1) * 32;

        const uint32_t baseA1 = sb + SM_XS
            + (uint32_t)(((m1 + (lane & 15)) * XS_W + ((lane >> 4) << 2)) * 4);
        const uint32_t baseB1 = sb + SM_W0S
            + (uint32_t)(((n1 + (lane & 7) + ((lane >> 4) << 3)) * W0S_W
                          + (((lane >> 3) & 1) << 2)) * 4);

        // X fragments for ALL k: 12 sets x 4 regs, loaded ONCE
        uint32_t xf[12][4];
        #pragma unroll
        for (int kk = 0; kk < 12; kk++)
            ldsm4(xf[kk][0], xf[kk][1], xf[kk][2], xf[kk][3], baseA1 + kk * 32);

        for (int c = 0; c < NCH; c++) {
            const int p = c & 1;
            CP_WAIT0();                 // this thread's w0(c) parts done
            BAR_SYNC(BINTA, 256);       // w0s visible to all of A

            float c1[4][4];
            #pragma unroll
            for (int j = 0; j < 4; j++)
                #pragma unroll
                for (int e = 0; e < 4; e++) c1[j][e] = 0.0f;

            #pragma unroll 4
            for (int kk = 0; kk < 12; kk++) {
                const uint32_t ko = kk * 32;
                uint32_t b00, b01, b10, b11, b20, b21, b30, b31;
                ldsm4(b00, b01, b10, b11, baseB1 + ko);          // j = 0,1
                ldsm4(b20, b21, b30, b31, baseB1 + 6400 + ko);   // j = 2,3
                mma16816(c1[0], xf[kk][0], xf[kk][1], xf[kk][2], xf[kk][3], b00, b01);
                mma16816(c1[1], xf[kk][0], xf[kk][1], xf[kk][2], xf[kk][3], b10, b11);
                mma16816(c1[2], xf[kk][0], xf[kk][1], xf[kk][2], xf[kk][3], b20, b21);
                mma16816(c1[3], xf[kk][0], xf[kk][1], xf[kk][2], xf[kk][3], b30, b31);
            }
            BAR_SYNC(BINTA, 256);       // all A done reading w0s
            if (c + 1 < NCH) load_w0(sb, c + 1, gtid);

            if (c >= 2) BAR_SYNC(BFREE(p), 512);   // hs[p] free (B done c-2)

            // bias + relu + fp16 -> hs[p]
            {
                uint32_t* hsp = hsw + p * 2304;
                const int hb = c * 64;
                #pragma unroll
                for (int j = 0; j < 4; j++) {
                    int n = n1 + j * 8 + q * 2;
                    float bb0 = b0s[hb + n], bb1 = b0s[hb + n + 1];
                    float v0 = fmaxf(c1[j][0] + bb0, 0.f);
                    float v1 = fmaxf(c1[j][1] + bb1, 0.f);
                    float v2 = fmaxf(c1[j][2] + bb0, 0.f);
                    float v3 = fmaxf(c1[j][3] + bb1, 0.f);
                    hsp[(m1 + r) * HS_W + (n >> 1)]     = pack2(v0, v1);
                    hsp[(m1 + r + 8) * HS_W + (n >> 1)] = pack2(v2, v3);
                }
            }
            BAR_ARRIVE(BFULL(p), 512);  // hs[p] published to B
        }
    } else {
        // ================= group B: GEMM2 consumer =================
        const int wB = w - 8;
        const int m2 = (wB >> 2) * 32;
        const int n2 = (wB & 3) * 64;

        const uint32_t baseA2 = sb + SM_HS
            + (uint32_t)(((m2 + (lane & 15)) * HS_W + ((lane >> 4) << 2)) * 4);
        const uint32_t baseB2 = sb + SM_W1S
            + (uint32_t)(((n2 + (lane & 7) + ((lane >> 4) << 3)) * W1S_W
                          + (((lane >> 3) & 1) << 2)) * 4);

        float acc2[16][4];
        #pragma unroll
        for (int j = 0; j < 16; j++)
            #pragma unroll
            for (int e = 0; e < 4; e++) acc2[j][e] = 0.0f;

        for (int c = 0; c < NCH; c++) {
            const int p = c & 1;
            CP_WAIT0();                 // this thread's w1(c) parts done
            BAR_SYNC(BINTB, 256);       // w1s visible to all of B
            BAR_SYNC(BFULL(p), 512);    // hs[p] ready

            const uint32_t hA = baseA2 + p * HSB;
            #pragma unroll
            for (int kk = 0; kk < 4; kk++) {
                const uint32_t ko = kk * 32;
                uint32_t a[2][4];
                ldsm4(a[0][0], a[0][1], a[0][2], a[0][3], hA + ko);          // f=0
                ldsm4(a[1][0], a[1][1], a[1][2], a[1][3], hA + 2304 + ko);   // f=1
                #pragma unroll
                for (int jp = 0; jp < 4; jp++) {
                    uint32_t c0, c1_, c2, c3;
                    ldsm4(c0, c1_, c2, c3, baseB2 + jp * 2304 + ko);
                    const int j0 = jp * 2;
                    #pragma unroll
                    for (int f = 0; f < 2; f++) {
                        mma16816(acc2[j0 * 2 + f],       a[f][0], a[f][1], a[f][2], a[f][3], c0, c1_);
                        mma16816(acc2[(j0 + 1) * 2 + f], a[f][0], a[f][1], a[f][2], a[f][3], c2, c3);
                    }
                }
            }
            BAR_SYNC(BINTB, 256);       // all B done reading w1s + hs[p]
            if (c + 1 < NCH) load_w1(sb, c + 1, gtid);
            if (c + 2 < NCH) BAR_ARRIVE(BFREE(p), 512);
        }

        // ---- epilogue: +b1, relu, store ----
        #pragma unroll
        for (int j = 0; j < 8; j++) {
            int n = n2 + j * 8 + q * 2;
            float bb0 = b1s[n], bb1 = b1s[n + 1];
            #pragma unroll
            for (int f = 0; f < 2; f++) {
                const int rowg = slice * 128 + tokbase + m2 + f * 16 + r;
                float2 o0, o1;
                o0.x = fmaxf(acc2[j * 2 + f][0] + bb0, 0.f);
                o0.y = fmaxf(acc2[j * 2 + f][1] + bb1, 0.f);
                o1.x = fmaxf(acc2[j * 2 + f][2] + bb0, 0.f);
                o1.y = fmaxf(acc2[j * 2 + f][3] + bb1, 0.f);
                *(float2*)(out + (size_t)rowg * 256 + n)       = o0;
                *(float2*)(out + (size_t)(rowg + 8) * 256 + n) = o1;
            }
        }
    }
}

extern "C" void kernel_launch(void* const* d_in, const int* in_sizes, int n_in,
                              void* d_out, int out_size)
{
    const float* x  = (const float*)d_in[0];
    const float* W0 = (const float*)d_in[1];
    const float* b0 = (const float*)d_in[2];
    const float* W1 = (const float*)d_in[3];
    const float* b1 = (const float*)d_in[4];
    float* out = (float*)d_out;

    static bool configured = false;
    if (!configured) {
        cudaFuncSetAttribute(mlp_kernel,
                             cudaFuncAttributeMaxDynamicSharedMemorySize, SM_TOTAL);
        configured = true;
    }
    prep_kernel<<<256, 256>>>(W0, W1);
    mlp_kernel<<<3072, 512, SM_TOTAL>>>(x, b0, b1, out);
}

// round 15
// speedup vs baseline: 1.1651x; 1.1651x over previous
#include <cuda_runtime.h>
#include <cuda_fp16.h>
#include <cstdint>

// Fused 2-layer MLP, pure fp16 mma.sync + LDSM, 2 CTAs/SM (R13 base) with
// explicit fragment double-buffering in both GEMM inner loops: LDSM(k+1)
// issues before mma(k) so the 29-cyc shared-load latency is pipelined.
//   out = relu(relu(X@W0+b0)@W1+b1); rel_err ~4.2e-4 (validated R9/R11/R13).

#define K1   192
#define HID  1024
#define EMB  256
#define NCH  16

#define XS_W  100     // words/row (100%32=4 -> conflict-free LDSM phases)
#define W0S_W 100
#define HS_W  36
#define W1S_W 36

// smem byte offsets (total 100 KB -> 2 CTAs/SM)
#define SM_B0S 0
#define SM_B1S 4096
#define SM_XS  5120                   // 64*400  = 25600
#define SM_W0S 30720                  // 64*400  = 25600
#define SM_HS  56320                  // 64*144  = 9216
#define SM_W1S 65536                  // 256*144 = 36864
#define SM_TOTAL 102400

__device__ __align__(16) __half g_B1[HID * K1];     // W0^T [n][k]
__device__ __align__(16) __half g_B2[EMB * HID];    // W1^T [n][k]

__device__ __forceinline__ void cpa16(uint32_t dst, const void* src) {
    asm volatile("cp.async.cg.shared.global [%0], [%1], 16;" :: "r"(dst), "l"(src) : "memory");
}
#define CP_COMMIT() asm volatile("cp.async.commit_group;" ::: "memory")
#define CP_WAIT1()  asm volatile("cp.async.wait_group 1;" ::: "memory")
#define CP_WAIT0()  asm volatile("cp.async.wait_group 0;" ::: "memory")

__device__ __forceinline__ uint32_t smem_u32(const void* p) {
    uint32_t a;
    asm("{ .reg .u64 t; cvta.to.shared.u64 t, %1; cvt.u32.u64 %0, t; }" : "=r"(a) : "l"(p));
    return a;
}

__device__ __forceinline__ void ldsm4(uint32_t& r0, uint32_t& r1, uint32_t& r2,
                                      uint32_t& r3, uint32_t addr)
{
    asm volatile("ldmatrix.sync.aligned.m8n8.x4.shared.b16 {%0,%1,%2,%3}, [%4];"
        : "=r"(r0), "=r"(r1), "=r"(r2), "=r"(r3) : "r"(addr));
}

__device__ __forceinline__ void mma16816(float* c,
    uint32_t a0, uint32_t a1, uint32_t a2, uint32_t a3, uint32_t b0, uint32_t b1)
{
    asm volatile("mma.sync.aligned.m16n8k16.row.col.f32.f16.f16.f32 "
        "{%0,%1,%2,%3}, {%4,%5,%6,%7}, {%8,%9}, {%0,%1,%2,%3};"
        : "+f"(c[0]), "+f"(c[1]), "+f"(c[2]), "+f"(c[3])
        : "r"(a0), "r"(a1), "r"(a2), "r"(a3), "r"(b0), "r"(b1));
}

__device__ __forceinline__ uint32_t pack2(float x, float y) {
    __half2 h = __halves2half2(__float2half_rn(x), __float2half_rn(y));
    return *(uint32_t*)&h;
}

// ---------------- weight prep: fp16, transposed to [n][k] ----------------
__global__ void prep_kernel(const float* __restrict__ W0, const float* __restrict__ W1) {
    int stride = gridDim.x * blockDim.x;
    int t0 = blockIdx.x * blockDim.x + threadIdx.x;
    for (int i = t0; i < HID * K1; i += stride) {
        int n = i / K1, k = i % K1;
        g_B1[n * K1 + k] = __float2half_rn(W0[k * HID + n]);
    }
    for (int i = t0; i < EMB * HID; i += stride) {
        int n = i / HID, k = i % HID;
        g_B2[n * HID + k] = __float2half_rn(W1[k * EMB + n]);
    }
}

// ---------------- chunk loaders (256 threads) ----------------
__device__ __forceinline__ void load_w0(uint32_t sb, int c, int tid) {
    const __half* base = g_B1 + (size_t)c * 64 * K1;
    #pragma unroll
    for (int i = tid; i < 1536; i += 256) {           // 64 rows x 24 x 16B
        int n = i / 24, u = i % 24;
        cpa16(sb + SM_W0S + n * 400 + u * 16, base + n * K1 + u * 8);
    }
    CP_COMMIT();
}
__device__ __forceinline__ void load_w1(uint32_t sb, int c, int tid) {
    const __half* base = g_B2 + c * 64;
    #pragma unroll
    for (int i = tid; i < 2048; i += 256) {           // 256 rows x 8 x 16B
        int n = i / 8, u = i % 8;
        cpa16(sb + SM_W1S + n * 144 + u * 16, base + n * HID + u * 8);
    }
    CP_COMMIT();
}

// ---------------- main fused kernel ----------------
__global__ void __launch_bounds__(256, 2)
mlp_kernel(const float* __restrict__ x, const float* __restrict__ b0,
           const float* __restrict__ b1, float* __restrict__ out)
{
    extern __shared__ char smem[];
    const uint32_t sb = smem_u32(smem);
    const int tid  = threadIdx.x;
    const int lane = tid & 31;
    const int w    = tid >> 5;
    const int r    = lane >> 2;
    const int q    = lane & 3;

    // GEMM1 warp tile 16x32; GEMM2 warp tile 32x64
    const int m1 = (w >> 1) * 16;
    const int n1 = (w & 1) * 32;
    const int m2 = (w >> 2) * 32;
    const int n2 = (w & 3) * 64;

    const int slice   = blockIdx.x >> 1;
    const int tokbase = (blockIdx.x & 1) * 64;

    uint32_t* xsw = (uint32_t*)(smem + SM_XS);
    uint32_t* hsw = (uint32_t*)(smem + SM_HS);
    float*    b0s = (float*)(smem + SM_B0S);
    float*    b1s = (float*)(smem + SM_B1S);

    // LDSM per-lane base addresses (bytes, shared space)
    const uint32_t baseA1 = sb + SM_XS
        + (uint32_t)(((m1 + (lane & 15)) * XS_W + ((lane >> 4) << 2)) * 4);
    const uint32_t baseA2 = sb + SM_HS
        + (uint32_t)(((m2 + (lane & 15)) * HS_W + ((lane >> 4) << 2)) * 4);
    const uint32_t baseB1 = sb + SM_W0S
        + (uint32_t)(((n1 + (lane & 7) + ((lane >> 4) << 3)) * W0S_W
                      + (((lane >> 3) & 1) << 2)) * 4);
    const uint32_t baseB2 = sb + SM_W1S
        + (uint32_t)(((n2 + (lane & 7) + ((lane >> 4) << 3)) * W1S_W
                      + (((lane >> 3) & 1) << 2)) * 4);

    // prefetch chunk 0 weights
    load_w0(sb, 0, tid);
    load_w1(sb, 0, tid);

    // X slice -> Xs (fp16, 96 words per row)
    {
        const float2* x2 = (const float2*)(x + (size_t)slice * 24576);
        #pragma unroll 4
        for (int i = tid; i < 6144; i += 256) {
            int m = i / 96, u = i % 96;
            int ch = u >> 5, bp = u & 31;
            float2 v = x2[(ch * 8192 + (tokbase + m) * 64) / 2 + bp];
            xsw[m * XS_W + ch * 32 + bp] = pack2(v.x, v.y);
        }
        for (int i = tid; i < 1024; i += 256) b0s[i] = b0[i];
        for (int i = tid; i < 256;  i += 256) b1s[i] = b1[i];
    }

    float acc2[16][4];
    #pragma unroll
    for (int j = 0; j < 16; j++)
        #pragma unroll
        for (int e = 0; e < 4; e++) acc2[j][e] = 0.0f;

    for (int c = 0; c < NCH; c++) {
        CP_WAIT1();                  // w0(c) resident (w1(c) may be in flight)
        __syncthreads();

        // ---- GEMM1: c1[16x32 per warp], k = 192, pipelined fragments ----
        float c1[4][4];
        #pragma unroll
        for (int j = 0; j < 4; j++)
            #pragma unroll
            for (int e = 0; e < 4; e++) c1[j][e] = 0.0f;

        {
            uint32_t Af[2][4], Bf[2][8];
            ldsm4(Af[0][0], Af[0][1], Af[0][2], Af[0][3], baseA1);
            ldsm4(Bf[0][0], Bf[0][1], Bf[0][2], Bf[0][3], baseB1);
            ldsm4(Bf[0][4], Bf[0][5], Bf[0][6], Bf[0][7], baseB1 + 6400);
            #pragma unroll
            for (int kk = 0; kk < 12; kk++) {
                const int cur = kk & 1, nxt = cur ^ 1;
                if (kk < 11) {
                    const uint32_t ko2 = (kk + 1) * 32;
                    ldsm4(Af[nxt][0], Af[nxt][1], Af[nxt][2], Af[nxt][3], baseA1 + ko2);
                    ldsm4(Bf[nxt][0], Bf[nxt][1], Bf[nxt][2], Bf[nxt][3], baseB1 + ko2);
                    ldsm4(Bf[nxt][4], Bf[nxt][5], Bf[nxt][6], Bf[nxt][7], baseB1 + 6400 + ko2);
                }
                mma16816(c1[0], Af[cur][0], Af[cur][1], Af[cur][2], Af[cur][3], Bf[cur][0], Bf[cur][1]);
                mma16816(c1[1], Af[cur][0], Af[cur][1], Af[cur][2], Af[cur][3], Bf[cur][2], Bf[cur][3]);
                mma16816(c1[2], Af[cur][0], Af[cur][1], Af[cur][2], Af[cur][3], Bf[cur][4], Bf[cur][5]);
                mma16816(c1[3], Af[cur][0], Af[cur][1], Af[cur][2], Af[cur][3], Bf[cur][6], Bf[cur][7]);
            }
        }

        // ---- bias + relu + fp16 -> hs ----
        {
            const int hb = c * 64;
            #pragma unroll
            for (int j = 0; j < 4; j++) {
                int n = n1 + j * 8 + q * 2;
                float bb0 = b0s[hb + n], bb1 = b0s[hb + n + 1];
                float v0 = fmaxf(c1[j][0] + bb0, 0.f);
                float v1 = fmaxf(c1[j][1] + bb1, 0.f);
                float v2 = fmaxf(c1[j][2] + bb0, 0.f);
                float v3 = fmaxf(c1[j][3] + bb1, 0.f);
                hsw[(m1 + r) * HS_W + (n >> 1)]     = pack2(v0, v1);
                hsw[(m1 + r + 8) * HS_W + (n >> 1)] = pack2(v2, v3);
            }
        }
        __syncthreads();             // w0s free, hs published
        if (c + 1 < NCH) load_w0(sb, c + 1, tid);

        if (c + 1 < NCH) { CP_WAIT1(); } else { CP_WAIT0(); }  // w1(c) resident
        __syncthreads();

        // ---- GEMM2: acc2[32x64 per warp] += hs @ w1s, pipelined fragments ----
        {
            uint32_t Aa[2][8];
            ldsm4(Aa[0][0], Aa[0][1], Aa[0][2], Aa[0][3], baseA2);
            ldsm4(Aa[0][4], Aa[0][5], Aa[0][6], Aa[0][7], baseA2 + 2304);
            #pragma unroll
            for (int kk = 0; kk < 4; kk++) {
                const int cur = kk & 1, nxt = cur ^ 1;
                const uint32_t ko = kk * 32;
                if (kk < 3) {
                    const uint32_t ko2 = (kk + 1) * 32;
                    ldsm4(Aa[nxt][0], Aa[nxt][1], Aa[nxt][2], Aa[nxt][3], baseA2 + ko2);
                    ldsm4(Aa[nxt][4], Aa[nxt][5], Aa[nxt][6], Aa[nxt][7], baseA2 + 2304 + ko2);
                }
                uint32_t Bb[2][4];
                ldsm4(Bb[0][0], Bb[0][1], Bb[0][2], Bb[0][3], baseB2 + ko);
                #pragma unroll
                for (int jp = 0; jp < 4; jp++) {
                    const int bc = jp & 1, bn = bc ^ 1;
                    if (jp < 3)
                        ldsm4(Bb[bn][0], Bb[bn][1], Bb[bn][2], Bb[bn][3],
                              baseB2 + (jp + 1) * 2304 + ko);
                    const int j0 = jp * 2;
                    #pragma unroll
                    for (int f = 0; f < 2; f++) {
                        mma16816(acc2[j0 * 2 + f],
                                 Aa[cur][f * 4 + 0], Aa[cur][f * 4 + 1],
                                 Aa[cur][f * 4 + 2], Aa[cur][f * 4 + 3],
                                 Bb[bc][0], Bb[bc][1]);
                        mma16816(acc2[(j0 + 1) * 2 + f],
                                 Aa[cur][f * 4 + 0], Aa[cur][f * 4 + 1],
                                 Aa[cur][f * 4 + 2], Aa[cur][f * 4 + 3],
                                 Bb[bc][2], Bb[bc][3]);
                    }
                }
            }
        }
        __syncthreads();             // w1s + hs free
        if (c + 1 < NCH) load_w1(sb, c + 1, tid);
    }

    // ---- epilogue: +b1, relu, store ----
    #pragma unroll
    for (int j = 0; j < 8; j++) {
        int n = n2 + j * 8 + q * 2;
        float bb0 = b1s[n], bb1 = b1s[n + 1];
        #pragma unroll
        for (int f = 0; f < 2; f++) {
            const int rowg = slice * 128 + tokbase + m2 + f * 16 + r;
            float2 o0, o1;
            o0.x = fmaxf(acc2[j * 2 + f][0] + bb0, 0.f);
            o0.y = fmaxf(acc2[j * 2 + f][1] + bb1, 0.f);
            o1.x = fmaxf(acc2[j * 2 + f][2] + bb0, 0.f);
            o1.y = fmaxf(acc2[j * 2 + f][3] + bb1, 0.f);
            *(float2*)(out + (size_t)rowg * 256 + n)       = o0;
            *(float2*)(out + (size_t)(rowg + 8) * 256 + n) = o1;
        }
    }
}

extern "C" void kernel_launch(void* const* d_in, const int* in_sizes, int n_in,
                              void* d_out, int out_size)
{
    const float* x  = (const float*)d_in[0];
    const float* W0 = (const float*)d_in[1];
    const float* b0 = (const float*)d_in[2];
    const float* W1 = (const float*)d_in[3];
    const float* b1 = (const float*)d_in[4];
    float* out = (float*)d_out;

    static bool configured = false;
    if (!configured) {
        cudaFuncSetAttribute(mlp_kernel,
                             cudaFuncAttributeMaxDynamicSharedMemorySize, SM_TOTAL);
        configured = true;
    }
    prep_kernel<<<256, 256>>>(W0, W1);
    mlp_kernel<<<3072, 256, SM_TOTAL>>>(x, b0, b1, out);
}